// round 16
// baseline (speedup 1.0000x reference)
#include <cuda_runtime.h>
#include <stdint.h>

#define NN 10000
#define EMAX 320000

// ---------------- device scratch (device-side references ONLY) ----------------
__device__ int g_rows[EMAX];
__device__ int g_cols[EMAX];
__device__ int g_deg[NN];            // zero at entry (static init + cleanup each launch)
__device__ int g_off[NN + 1];
__device__ int g_cursor[NN];
__device__ int g_srclist[EMAX + NN];
__device__ __align__(16) float g_h1[NN * 32];
__device__ __align__(16) float g_es1[NN * 8];
__device__ __align__(16) float g_ed1[NN * 8];
__device__ __align__(16) float g_h2[NN * 16];
__device__ __align__(16) float g_es2[NN * 4];
__device__ __align__(16) float g_ed2[NN * 4];
__device__ __align__(16) float g_h3[NN * 8];
__device__ __align__(16) float g_es3[NN * 2];
__device__ __align__(16) float g_ed3[NN * 2];
__device__ __align__(16) float g_x6[NN * 8];
__device__ __align__(16) unsigned g_bitmap[((size_t)NN * NN) / 32];  // zero at entry
__device__ int g_degc[NN];
__device__ __align__(16) float g_agg[NN * 8];

// ---------------- kernel 1: edge decode + degree hist + layer-1 transform ----------------
__global__ void k_edges_t1(const int* __restrict__ q, int E,
                           const float* __restrict__ x1, const float* __restrict__ W1,
                           const float* __restrict__ as1, const float* __restrict__ ad1) {
    __shared__ float sW[10 * 32];
    __shared__ float sas[32], sad[32];
    int tid0 = blockIdx.x * blockDim.x;
    int i = tid0 + threadIdx.x;
    if (tid0 < NN) {   // uniform per block
        for (int t = threadIdx.x; t < 320; t += blockDim.x) sW[t] = W1[t];
        if (threadIdx.x < 32) { sas[threadIdx.x] = as1[threadIdx.x]; sad[threadIdx.x] = ad1[threadIdx.x]; }
        __syncthreads();
    }
    // --- edges: decode (dtype sniffed from zero high-words of int64) + hist ---
    if (i < E) {
        bool is64 = (q[1] == 0 && q[3] == 0 && q[5] == 0);
        int r, c;
        if (is64) { const long long* p = (const long long*)q; r = (int)p[i]; c = (int)p[E + i]; }
        else      { r = q[i]; c = q[E + i]; }
        g_rows[i] = r;
        g_cols[i] = c;
        atomicAdd(&g_deg[c], 1);
    }
    // --- layer-1 transform: h1 = x1@W1, es1/ed1 einsums ---
    if (i < NN) {
        float xi[10];
#pragma unroll
        for (int k = 0; k < 10; k++) xi[k] = x1[i * 10 + k];
        float es[8], ed[8];
#pragma unroll
        for (int h = 0; h < 8; h++) { es[h] = 0.f; ed[h] = 0.f; }
#pragma unroll
        for (int hc = 0; hc < 32; hc++) {
            float acc = 0.f;
#pragma unroll
            for (int k = 0; k < 10; k++) acc += xi[k] * sW[k * 32 + hc];
            g_h1[i * 32 + hc] = acc;
            es[hc >> 2] += acc * sas[hc];
            ed[hc >> 2] += acc * sad[hc];
        }
#pragma unroll
        for (int h = 0; h < 8; h++) { g_es1[i * 8 + h] = es[h]; g_ed1[i * 8 + h] = ed[h]; }
    }
}

// ---------------- kernel 2: exclusive scan of (deg+1) -> CSR offsets ----------------
__global__ void k_scan() {
    __shared__ int sh[1024];
    int tid = threadIdx.x;
    const int CH = (NN + 1023) / 1024;
    int base = tid * CH;
    int s = 0;
    for (int i = 0; i < CH; i++) {
        int j = base + i;
        if (j < NN) s += g_deg[j] + 1;   // +1 = appended self-loop
    }
    sh[tid] = s;
    __syncthreads();
    for (int ofs = 1; ofs < 1024; ofs <<= 1) {
        int v = (tid >= ofs) ? sh[tid - ofs] : 0;
        __syncthreads();
        sh[tid] += v;
        __syncthreads();
    }
    int run = (tid == 0) ? 0 : sh[tid - 1];
    for (int i = 0; i < CH; i++) {
        int j = base + i;
        if (j < NN) {
            g_off[j] = run;
            g_cursor[j] = run;
            run += g_deg[j] + 1;
        }
    }
    if (tid == 1023) g_off[NN] = sh[1023];
}

// ---------------- kernel 3: scatter sources into CSR-by-dst ----------------
__global__ void k_scatter(int E) {
    int i = blockIdx.x * blockDim.x + threadIdx.x;
    if (i >= E + NN) return;
    int r, c;
    if (i < E) { r = g_rows[i]; c = g_cols[i]; }
    else       { r = i - E;     c = r; }       // self-loop
    int p = atomicAdd(&g_cursor[c], 1);
    g_srclist[p] = r;
}

// ---------------- kernel 4: aggregate L1 (softmax) + transform L2 fused ----------------
// G=8 lanes per node. After shfl reduction ALL lanes hold the full output row,
// so the next layer's x@W + einsums are computed in-register, no x3 round-trip.
__global__ void k_a1t2(const float* __restrict__ bias, const float* __restrict__ W2,
                       const float* __restrict__ as2, const float* __restrict__ ad2) {
    __shared__ float sW[32 * 16];
    __shared__ float sas[16], sad[16];
    for (int t = threadIdx.x; t < 512; t += blockDim.x) sW[t] = W2[t];
    if (threadIdx.x < 16) { sas[threadIdx.x] = as2[threadIdx.x]; sad[threadIdx.x] = ad2[threadIdx.x]; }
    __syncthreads();

    int gt = blockIdx.x * blockDim.x + threadIdx.x;
    int node = gt >> 3, lane = gt & 7;
    if (node >= NN) return;
    int beg = g_off[node], end = g_off[node + 1];

    float edv[8];
    {
        float4 a = *(const float4*)&g_ed1[node * 8];
        float4 b = *(const float4*)&g_ed1[node * 8 + 4];
        edv[0] = a.x; edv[1] = a.y; edv[2] = a.z; edv[3] = a.w;
        edv[4] = b.x; edv[5] = b.y; edv[6] = b.z; edv[7] = b.w;
    }
    float denom[8], acc[32];
#pragma unroll
    for (int h = 0; h < 8; h++) denom[h] = 0.f;
#pragma unroll
    for (int j = 0; j < 32; j++) acc[j] = 0.f;

    for (int e = beg + lane; e < end; e += 8) {
        int s = g_srclist[e];
        float4 ea = *(const float4*)&g_es1[s * 8];
        float4 eb = *(const float4*)&g_es1[s * 8 + 4];
        float esv[8] = {ea.x, ea.y, ea.z, ea.w, eb.x, eb.y, eb.z, eb.w};
        const float4* hp = (const float4*)&g_h1[s * 32];
#pragma unroll
        for (int h = 0; h < 8; h++) {
            float v = esv[h] + edv[h];
            v = v > 0.f ? v : 0.2f * v;
            float ex = expf(v);
            denom[h] += ex;
            float4 hv = hp[h];
            acc[h * 4 + 0] += ex * hv.x;
            acc[h * 4 + 1] += ex * hv.y;
            acc[h * 4 + 2] += ex * hv.z;
            acc[h * 4 + 3] += ex * hv.w;
        }
    }
#pragma unroll
    for (int o = 1; o < 8; o <<= 1) {
#pragma unroll
        for (int h = 0; h < 8; h++) denom[h] += __shfl_xor_sync(0xffffffffu, denom[h], o);
#pragma unroll
        for (int j = 0; j < 32; j++) acc[j] += __shfl_xor_sync(0xffffffffu, acc[j], o);
    }
    float outv[32];
#pragma unroll
    for (int j = 0; j < 32; j++) {
        float v = acc[j] / denom[j >> 2] + bias[j];
        outv[j] = v > 0.f ? v : 0.f;   // x3 row, in registers on all lanes
    }
    // transform L2: lane computes outputs o = 2*lane, 2*lane+1
    float esn[4] = {0, 0, 0, 0}, edn[4] = {0, 0, 0, 0};
    float hv[2];
#pragma unroll
    for (int t = 0; t < 2; t++) {
        int o = 2 * lane + t;
        float a = 0.f;
#pragma unroll
        for (int k = 0; k < 32; k++) a += outv[k] * sW[k * 16 + o];
        hv[t] = a;
        esn[o >> 2] += a * sas[o];
        edn[o >> 2] += a * sad[o];
    }
#pragma unroll
    for (int o = 1; o < 8; o <<= 1) {
#pragma unroll
        for (int h = 0; h < 4; h++) {
            esn[h] += __shfl_xor_sync(0xffffffffu, esn[h], o);
            edn[h] += __shfl_xor_sync(0xffffffffu, edn[h], o);
        }
    }
    *(float2*)&g_h2[node * 16 + 2 * lane] = make_float2(hv[0], hv[1]);
    if (lane < 4) { g_es2[node * 4 + lane] = esn[lane]; g_ed2[node * 4 + lane] = edn[lane]; }
}

// ---------------- kernel 5: aggregate L2 + transform L3 fused ----------------
__global__ void k_a2t3(const float* __restrict__ bias, const float* __restrict__ W3,
                       const float* __restrict__ as3, const float* __restrict__ ad3) {
    __shared__ float sW[16 * 8];
    __shared__ float sas[8], sad[8];
    for (int t = threadIdx.x; t < 128; t += blockDim.x) sW[t] = W3[t];
    if (threadIdx.x < 8) { sas[threadIdx.x] = as3[threadIdx.x]; sad[threadIdx.x] = ad3[threadIdx.x]; }
    __syncthreads();

    int gt = blockIdx.x * blockDim.x + threadIdx.x;
    int node = gt >> 3, lane = gt & 7;
    if (node >= NN) return;
    int beg = g_off[node], end = g_off[node + 1];

    float edv[4];
    {
        float4 a = *(const float4*)&g_ed2[node * 4];
        edv[0] = a.x; edv[1] = a.y; edv[2] = a.z; edv[3] = a.w;
    }
    float denom[4], acc[16];
#pragma unroll
    for (int h = 0; h < 4; h++) denom[h] = 0.f;
#pragma unroll
    for (int j = 0; j < 16; j++) acc[j] = 0.f;

    for (int e = beg + lane; e < end; e += 8) {
        int s = g_srclist[e];
        float4 ea = *(const float4*)&g_es2[s * 4];
        float esv[4] = {ea.x, ea.y, ea.z, ea.w};
        const float4* hp = (const float4*)&g_h2[s * 16];
#pragma unroll
        for (int h = 0; h < 4; h++) {
            float v = esv[h] + edv[h];
            v = v > 0.f ? v : 0.2f * v;
            float ex = expf(v);
            denom[h] += ex;
            float4 hv = hp[h];
            acc[h * 4 + 0] += ex * hv.x;
            acc[h * 4 + 1] += ex * hv.y;
            acc[h * 4 + 2] += ex * hv.z;
            acc[h * 4 + 3] += ex * hv.w;
        }
    }
#pragma unroll
    for (int o = 1; o < 8; o <<= 1) {
#pragma unroll
        for (int h = 0; h < 4; h++) denom[h] += __shfl_xor_sync(0xffffffffu, denom[h], o);
#pragma unroll
        for (int j = 0; j < 16; j++) acc[j] += __shfl_xor_sync(0xffffffffu, acc[j], o);
    }
    float outv[16];
#pragma unroll
    for (int j = 0; j < 16; j++) {
        float v = acc[j] / denom[j >> 2] + bias[j];
        outv[j] = v > 0.f ? v : 0.f;   // x4 row
    }
    // transform L3: lane computes output o = lane (8 outputs)
    float esn[2] = {0, 0}, edn[2] = {0, 0};
    int o = lane;
    float a = 0.f;
#pragma unroll
    for (int k = 0; k < 16; k++) a += outv[k] * sW[k * 8 + o];
    esn[o >> 2] += a * sas[o];
    edn[o >> 2] += a * sad[o];
#pragma unroll
    for (int of = 1; of < 8; of <<= 1) {
#pragma unroll
        for (int h = 0; h < 2; h++) {
            esn[h] += __shfl_xor_sync(0xffffffffu, esn[h], of);
            edn[h] += __shfl_xor_sync(0xffffffffu, edn[h], of);
        }
    }
    g_h3[node * 8 + lane] = a;
    if (lane < 2) { g_es3[node * 2 + lane] = esn[lane]; g_ed3[node * 2 + lane] = edn[lane]; }
}

// ---------------- kernel 6: aggregate L3 + final-scoring init fused ----------------
__global__ void k_a3f(const float* __restrict__ bias) {
    int gt = blockIdx.x * blockDim.x + threadIdx.x;
    int node = gt >> 3, lane = gt & 7;
    if (node >= NN) return;
    int beg = g_off[node], end = g_off[node + 1];

    float2 ed = *(const float2*)&g_ed3[node * 2];
    float edv[2] = {ed.x, ed.y};
    float denom[2] = {0.f, 0.f};
    float acc[8];
#pragma unroll
    for (int j = 0; j < 8; j++) acc[j] = 0.f;

    for (int e = beg + lane; e < end; e += 8) {
        int s = g_srclist[e];
        float2 ea = *(const float2*)&g_es3[s * 2];
        float esv[2] = {ea.x, ea.y};
        const float4* hp = (const float4*)&g_h3[s * 8];
#pragma unroll
        for (int h = 0; h < 2; h++) {
            float v = esv[h] + edv[h];
            v = v > 0.f ? v : 0.2f * v;
            float ex = expf(v);
            denom[h] += ex;
            float4 hv = hp[h];
            acc[h * 4 + 0] += ex * hv.x;
            acc[h * 4 + 1] += ex * hv.y;
            acc[h * 4 + 2] += ex * hv.z;
            acc[h * 4 + 3] += ex * hv.w;
        }
    }
#pragma unroll
    for (int o = 1; o < 8; o <<= 1) {
#pragma unroll
        for (int h = 0; h < 2; h++) denom[h] += __shfl_xor_sync(0xffffffffu, denom[h], o);
#pragma unroll
        for (int j = 0; j < 8; j++) acc[j] += __shfl_xor_sync(0xffffffffu, acc[j], o);
    }
    float outv[8];
#pragma unroll
    for (int j = 0; j < 8; j++) {
        float v = acc[j] / denom[j >> 2] + bias[j];
        outv[j] = v > 0.f ? v : 0.f;   // x6 row
    }
    if (lane == 0) {
        *(float4*)&g_x6[node * 8]  = make_float4(outv[0], outv[1], outv[2], outv[3]);
        *(float4*)&g_agg[node * 8] = make_float4(outv[0], outv[1], outv[2], outv[3]);
    } else if (lane == 1) {
        *(float4*)&g_x6[node * 8 + 4]  = make_float4(outv[4], outv[5], outv[6], outv[7]);
        *(float4*)&g_agg[node * 8 + 4] = make_float4(outv[4], outv[5], outv[6], outv[7]);
    } else if (lane == 2) {
        g_degc[node] = 1;
    } else if (lane == 3) {
        size_t bit = (size_t)node * NN + node;
        g_bitmap[bit >> 5] = 1u << (bit & 31);   // diag bit (before dedup kernel)
    }
}

// ---------------- kernel 7: dedup scatter (bitmap first-touch) ----------------
__global__ void k_dedup(int E) {
    int e = blockIdx.x * blockDim.x + threadIdx.x;
    if (e >= E) return;
    int r = g_rows[e], c = g_cols[e];
    size_t bit = (size_t)r * NN + c;
    unsigned mask = 1u << (bit & 31);
    unsigned old = atomicOr(&g_bitmap[bit >> 5], mask);
    if (!(old & mask)) {
        atomicAdd(&g_degc[r], 1);
        const float4* xp = (const float4*)&g_x6[c * 8];
        float4 a = xp[0], b = xp[1];
        atomicAdd(&g_agg[r * 8 + 0], a.x);
        atomicAdd(&g_agg[r * 8 + 1], a.y);
        atomicAdd(&g_agg[r * 8 + 2], a.z);
        atomicAdd(&g_agg[r * 8 + 3], a.w);
        atomicAdd(&g_agg[r * 8 + 4], b.x);
        atomicAdd(&g_agg[r * 8 + 5], b.y);
        atomicAdd(&g_agg[r * 8 + 6], b.z);
        atomicAdd(&g_agg[r * 8 + 7], b.w);
    }
}

// ---------------- kernel 8: final score + touched-state cleanup ----------------
// Resets exactly the bitmap words set this launch (edges + diag) and g_deg,
// restoring the all-zero invariant for the next graph replay.
__global__ void k_final_cleanup(const float* __restrict__ x1,
                                const float* __restrict__ lin2w,
                                float* __restrict__ out, int E) {
    int i = blockIdx.x * blockDim.x + threadIdx.x;
    if (i < NN) {
        float inv = 1.0f / (float)g_degc[i];
        float r2 = 0.f, gl = 0.f;
#pragma unroll
        for (int c = 0; c < 8; c++) {
            float a = g_agg[i * 8 + c];
            r2 += g_x6[i * 8 + c] * a;
            gl += (inv * a) * lin2w[c];
        }
        out[i] = r2 * inv + x1[i * 10] + gl;
    }
    if (i < E) {
        size_t bit = (size_t)g_rows[i] * NN + g_cols[i];
        g_bitmap[bit >> 5] = 0u;
    } else if (i < E + NN) {
        int n = i - E;
        size_t bit = (size_t)n * NN + (size_t)n;
        g_bitmap[bit >> 5] = 0u;
        g_deg[n] = 0;
    }
}

// ---------------- launch ----------------
extern "C" void kernel_launch(void* const* d_in, const int* in_sizes, int n_in,
                              void* d_out, int out_size) {
    const float* x1    = (const float*)d_in[0];
    const int*   eidx  = (const int*)d_in[2];
    const float* W1    = (const float*)d_in[4];
    const float* as1   = (const float*)d_in[5];
    const float* ad1   = (const float*)d_in[6];
    const float* b1    = (const float*)d_in[7];
    const float* W2    = (const float*)d_in[8];
    const float* as2   = (const float*)d_in[9];
    const float* ad2   = (const float*)d_in[10];
    const float* b2    = (const float*)d_in[11];
    const float* W3    = (const float*)d_in[12];
    const float* as3   = (const float*)d_in[13];
    const float* ad3   = (const float*)d_in[14];
    const float* b3    = (const float*)d_in[15];
    const float* lin2w = (const float*)d_in[16];
    float* out = (float*)d_out;

    int E = in_sizes[2] / 2;
    if (E > EMAX) E = EMAX;

    const int TB = 256;
    int gE  = (E + TB - 1) / TB;
    int gEN = (E + NN + TB - 1) / TB;
    int gW  = (NN * 8 + TB - 1) / TB;   // G=8 lanes per node

    k_edges_t1<<<gE, TB>>>(eidx, E, x1, W1, as1, ad1);
    k_scan<<<1, 1024>>>();
    k_scatter<<<gEN, TB>>>(E);
    k_a1t2<<<gW, TB>>>(b1, W2, as2, ad2);
    k_a2t3<<<gW, TB>>>(b2, W3, as3, ad3);
    k_a3f<<<gW, TB>>>(b3);
    k_dedup<<<gE, TB>>>(E);
    k_final_cleanup<<<gEN, TB>>>(x1, lin2w, out, E);
}

// round 17
// speedup vs baseline: 1.4092x; 1.4092x over previous
#include <cuda_runtime.h>
#include <stdint.h>

#define NN 10000
#define EMAX 320000

// ---------------- device scratch (device-side references ONLY) ----------------
__device__ int g_rows[EMAX];
__device__ int g_cols[EMAX];
__device__ int g_deg[NN];            // zero at entry (static zero + per-launch cleanup)
__device__ int g_off[NN + 1];
__device__ int g_cursor[NN];
__device__ int g_srclist[EMAX + NN];
__device__ __align__(16) float g_h1[NN * 32];
__device__ __align__(16) float g_es1[NN * 8];
__device__ __align__(16) float g_ed1[NN * 8];
__device__ __align__(16) float g_x3[NN * 32];
__device__ __align__(16) float g_h2[NN * 16];
__device__ __align__(16) float g_es2[NN * 4];
__device__ __align__(16) float g_ed2[NN * 4];
__device__ __align__(16) float g_x4[NN * 16];
__device__ __align__(16) float g_h3[NN * 8];
__device__ __align__(16) float g_es3[NN * 2];
__device__ __align__(16) float g_ed3[NN * 2];
__device__ __align__(16) float g_x6[NN * 8];
__device__ __align__(16) unsigned g_bitmap[((size_t)NN * NN) / 32];  // zero at entry
__device__ int g_degc[NN];
__device__ __align__(16) float g_agg[NN * 8];

// ---------------- kernel 1: edge decode + degree hist + layer-1 transform ----------------
// E == NN*32 for this dataset, so one grid covers both jobs with full chip spread.
// t1 is thread-per-output: node = i>>5, output = i&31.
__global__ void k_edges_t1(const int* __restrict__ q, int E,
                           const float* __restrict__ x1, const float* __restrict__ W1,
                           const float* __restrict__ as1, const float* __restrict__ ad1) {
    __shared__ float sW[10 * 32];
    __shared__ float sas[32], sad[32];
    for (int t = threadIdx.x; t < 320; t += blockDim.x) sW[t] = W1[t];
    if (threadIdx.x < 32) { sas[threadIdx.x] = as1[threadIdx.x]; sad[threadIdx.x] = ad1[threadIdx.x]; }
    __syncthreads();
    int i = blockIdx.x * blockDim.x + threadIdx.x;
    if (i < E) {   // decode (int64 sniffed via zero high words) + degree histogram
        bool is64 = (q[1] == 0 && q[3] == 0 && q[5] == 0);
        int r, c;
        if (is64) { const long long* p = (const long long*)q; r = (int)p[i]; c = (int)p[E + i]; }
        else      { r = q[i]; c = q[E + i]; }
        g_rows[i] = r;
        g_cols[i] = c;
        atomicAdd(&g_deg[c], 1);
    }
    if (i < NN * 32) {   // t1: one output element per thread
        int node = i >> 5, lane = i & 31;
        const float* xr = &x1[node * 10];
        float a = 0.f;
#pragma unroll
        for (int k = 0; k < 10; k++) a += xr[k] * sW[k * 32 + lane];
        g_h1[i] = a;
        float es = a * sas[lane], ed = a * sad[lane];
        es += __shfl_xor_sync(0xffffffffu, es, 1);
        es += __shfl_xor_sync(0xffffffffu, es, 2);
        ed += __shfl_xor_sync(0xffffffffu, ed, 1);
        ed += __shfl_xor_sync(0xffffffffu, ed, 2);
        if ((lane & 3) == 0) {
            g_es1[node * 8 + (lane >> 2)] = es;
            g_ed1[node * 8 + (lane >> 2)] = ed;
        }
    }
}

// ---------------- kernel 2: exclusive scan of (deg+1) -> CSR offsets ----------------
__global__ void k_scan() {
    __shared__ int sh[1024];
    int tid = threadIdx.x;
    const int CH = (NN + 1023) / 1024;
    int base = tid * CH;
    int s = 0;
    for (int i = 0; i < CH; i++) {
        int j = base + i;
        if (j < NN) s += g_deg[j] + 1;   // +1: appended self-loop
    }
    sh[tid] = s;
    __syncthreads();
    for (int ofs = 1; ofs < 1024; ofs <<= 1) {
        int v = (tid >= ofs) ? sh[tid - ofs] : 0;
        __syncthreads();
        sh[tid] += v;
        __syncthreads();
    }
    int run = (tid == 0) ? 0 : sh[tid - 1];
    for (int i = 0; i < CH; i++) {
        int j = base + i;
        if (j < NN) {
            g_off[j] = run;
            g_cursor[j] = run;
            run += g_deg[j] + 1;
        }
    }
    if (tid == 1023) g_off[NN] = sh[1023];
}

// ---------------- kernel 3: scatter sources into CSR-by-dst ----------------
__global__ void k_scatter(int E) {
    int i = blockIdx.x * blockDim.x + threadIdx.x;
    if (i >= E + NN) return;
    int r, c;
    if (i < E) { r = g_rows[i]; c = g_cols[i]; }
    else       { r = i - E;     c = r; }   // self-loop
    int p = atomicAdd(&g_cursor[c], 1);
    g_srclist[p] = r;
}

// ---------------- kernel 4: aggregate L1 (warp per node, single-pass softmax) ----------------
__global__ void k_a1(const float* __restrict__ bias) {
    int gt = blockIdx.x * blockDim.x + threadIdx.x;
    int node = gt >> 5, lane = gt & 31;
    if (node >= NN) return;
    int beg = g_off[node], end = g_off[node + 1];

    float edv[8];
    {
        float4 a = *(const float4*)&g_ed1[node * 8];
        float4 b = *(const float4*)&g_ed1[node * 8 + 4];
        edv[0] = a.x; edv[1] = a.y; edv[2] = a.z; edv[3] = a.w;
        edv[4] = b.x; edv[5] = b.y; edv[6] = b.z; edv[7] = b.w;
    }
    float denom[8], acc[32];
#pragma unroll
    for (int h = 0; h < 8; h++) denom[h] = 0.f;
#pragma unroll
    for (int j = 0; j < 32; j++) acc[j] = 0.f;

    for (int e = beg + lane; e < end; e += 32) {
        int s = g_srclist[e];
        float4 ea = *(const float4*)&g_es1[s * 8];
        float4 eb = *(const float4*)&g_es1[s * 8 + 4];
        float esv[8] = {ea.x, ea.y, ea.z, ea.w, eb.x, eb.y, eb.z, eb.w};
        const float4* hp = (const float4*)&g_h1[s * 32];
#pragma unroll
        for (int h = 0; h < 8; h++) {
            float v = esv[h] + edv[h];
            v = v > 0.f ? v : 0.2f * v;        // leaky relu
            float ex = __expf(v);              // fast exp (err ~1e-7 rel, fine vs 1e-3)
            denom[h] += ex;
            float4 hv = hp[h];
            acc[h * 4 + 0] += ex * hv.x;
            acc[h * 4 + 1] += ex * hv.y;
            acc[h * 4 + 2] += ex * hv.z;
            acc[h * 4 + 3] += ex * hv.w;
        }
    }
#pragma unroll
    for (int o = 1; o < 32; o <<= 1) {
#pragma unroll
        for (int h = 0; h < 8; h++) denom[h] += __shfl_xor_sync(0xffffffffu, denom[h], o);
#pragma unroll
        for (int j = 0; j < 32; j++) acc[j] += __shfl_xor_sync(0xffffffffu, acc[j], o);
    }
    float v = acc[lane] / denom[lane >> 2] + bias[lane];
    g_x3[node * 32 + lane] = v > 0.f ? v : 0.f;
}

// ---------------- kernel 5: transform L2 (thread-per-output, G'=16) ----------------
__global__ void k_t2(const float* __restrict__ W2,
                     const float* __restrict__ as2, const float* __restrict__ ad2) {
    __shared__ float sW[32 * 16];
    __shared__ float sas[16], sad[16];
    for (int t = threadIdx.x; t < 512; t += blockDim.x) sW[t] = W2[t];
    if (threadIdx.x < 16) { sas[threadIdx.x] = as2[threadIdx.x]; sad[threadIdx.x] = ad2[threadIdx.x]; }
    __syncthreads();
    int gt = blockIdx.x * blockDim.x + threadIdx.x;
    int node = gt >> 4, lane = gt & 15;
    if (node >= NN) return;
    const float* xr = &g_x3[node * 32];
    float a = 0.f;
#pragma unroll
    for (int k = 0; k < 32; k++) a += xr[k] * sW[k * 16 + lane];
    g_h2[node * 16 + lane] = a;
    float es = a * sas[lane], ed = a * sad[lane];
    es += __shfl_xor_sync(0xffffffffu, es, 1);
    es += __shfl_xor_sync(0xffffffffu, es, 2);
    ed += __shfl_xor_sync(0xffffffffu, ed, 1);
    ed += __shfl_xor_sync(0xffffffffu, ed, 2);
    if ((lane & 3) == 0) {
        g_es2[node * 4 + (lane >> 2)] = es;
        g_ed2[node * 4 + (lane >> 2)] = ed;
    }
}

// ---------------- kernel 6: aggregate L2 ----------------
__global__ void k_a2(const float* __restrict__ bias) {
    int gt = blockIdx.x * blockDim.x + threadIdx.x;
    int node = gt >> 5, lane = gt & 31;
    if (node >= NN) return;
    int beg = g_off[node], end = g_off[node + 1];

    float edv[4];
    {
        float4 a = *(const float4*)&g_ed2[node * 4];
        edv[0] = a.x; edv[1] = a.y; edv[2] = a.z; edv[3] = a.w;
    }
    float denom[4], acc[16];
#pragma unroll
    for (int h = 0; h < 4; h++) denom[h] = 0.f;
#pragma unroll
    for (int j = 0; j < 16; j++) acc[j] = 0.f;

    for (int e = beg + lane; e < end; e += 32) {
        int s = g_srclist[e];
        float4 ea = *(const float4*)&g_es2[s * 4];
        float esv[4] = {ea.x, ea.y, ea.z, ea.w};
        const float4* hp = (const float4*)&g_h2[s * 16];
#pragma unroll
        for (int h = 0; h < 4; h++) {
            float v = esv[h] + edv[h];
            v = v > 0.f ? v : 0.2f * v;
            float ex = __expf(v);
            denom[h] += ex;
            float4 hv = hp[h];
            acc[h * 4 + 0] += ex * hv.x;
            acc[h * 4 + 1] += ex * hv.y;
            acc[h * 4 + 2] += ex * hv.z;
            acc[h * 4 + 3] += ex * hv.w;
        }
    }
#pragma unroll
    for (int o = 1; o < 32; o <<= 1) {
#pragma unroll
        for (int h = 0; h < 4; h++) denom[h] += __shfl_xor_sync(0xffffffffu, denom[h], o);
#pragma unroll
        for (int j = 0; j < 16; j++) acc[j] += __shfl_xor_sync(0xffffffffu, acc[j], o);
    }
    if (lane < 16) {
        float v = acc[lane] / denom[lane >> 2] + bias[lane];
        g_x4[node * 16 + lane] = v > 0.f ? v : 0.f;
    }
}

// ---------------- kernel 7: transform L3 (thread-per-output, G'=8) ----------------
__global__ void k_t3(const float* __restrict__ W3,
                     const float* __restrict__ as3, const float* __restrict__ ad3) {
    __shared__ float sW[16 * 8];
    __shared__ float sas[8], sad[8];
    for (int t = threadIdx.x; t < 128; t += blockDim.x) sW[t] = W3[t];
    if (threadIdx.x < 8) { sas[threadIdx.x] = as3[threadIdx.x]; sad[threadIdx.x] = ad3[threadIdx.x]; }
    __syncthreads();
    int gt = blockIdx.x * blockDim.x + threadIdx.x;
    int node = gt >> 3, lane = gt & 7;
    if (node >= NN) return;
    const float* xr = &g_x4[node * 16];
    float a = 0.f;
#pragma unroll
    for (int k = 0; k < 16; k++) a += xr[k] * sW[k * 8 + lane];
    g_h3[node * 8 + lane] = a;
    float es = a * sas[lane], ed = a * sad[lane];
    es += __shfl_xor_sync(0xffffffffu, es, 1);
    es += __shfl_xor_sync(0xffffffffu, es, 2);
    ed += __shfl_xor_sync(0xffffffffu, ed, 1);
    ed += __shfl_xor_sync(0xffffffffu, ed, 2);
    if ((lane & 3) == 0) {
        g_es3[node * 2 + (lane >> 2)] = es;
        g_ed3[node * 2 + (lane >> 2)] = ed;
    }
}

// ---------------- kernel 8: aggregate L3 + final-scoring init ----------------
__global__ void k_a3f(const float* __restrict__ bias) {
    int gt = blockIdx.x * blockDim.x + threadIdx.x;
    int node = gt >> 5, lane = gt & 31;
    if (node >= NN) return;
    int beg = g_off[node], end = g_off[node + 1];

    float2 ed = *(const float2*)&g_ed3[node * 2];
    float edv[2] = {ed.x, ed.y};
    float denom[2] = {0.f, 0.f};
    float acc[8];
#pragma unroll
    for (int j = 0; j < 8; j++) acc[j] = 0.f;

    for (int e = beg + lane; e < end; e += 32) {
        int s = g_srclist[e];
        float2 ea = *(const float2*)&g_es3[s * 2];
        float esv[2] = {ea.x, ea.y};
        const float4* hp = (const float4*)&g_h3[s * 8];
#pragma unroll
        for (int h = 0; h < 2; h++) {
            float v = esv[h] + edv[h];
            v = v > 0.f ? v : 0.2f * v;
            float ex = __expf(v);
            denom[h] += ex;
            float4 hv = hp[h];
            acc[h * 4 + 0] += ex * hv.x;
            acc[h * 4 + 1] += ex * hv.y;
            acc[h * 4 + 2] += ex * hv.z;
            acc[h * 4 + 3] += ex * hv.w;
        }
    }
#pragma unroll
    for (int o = 1; o < 32; o <<= 1) {
#pragma unroll
        for (int h = 0; h < 2; h++) denom[h] += __shfl_xor_sync(0xffffffffu, denom[h], o);
#pragma unroll
        for (int j = 0; j < 8; j++) acc[j] += __shfl_xor_sync(0xffffffffu, acc[j], o);
    }
    if (lane < 8) {
        float v = acc[lane] / denom[lane >> 2] + bias[lane];
        v = v > 0.f ? v : 0.f;
        g_x6[node * 8 + lane] = v;
        g_agg[node * 8 + lane] = v;    // diag contribution of adj@x6
    } else if (lane == 8) {
        g_degc[node] = 1;
    } else if (lane == 9) {
        size_t bit = (size_t)node * NN + node;
        g_bitmap[bit >> 5] = 1u << (bit & 31);   // diag bit
    }
}

// ---------------- kernel 9: dedup scatter (bitmap first-touch) ----------------
__global__ void k_dedup(int E) {
    int e = blockIdx.x * blockDim.x + threadIdx.x;
    if (e >= E) return;
    int r = g_rows[e], c = g_cols[e];
    size_t bit = (size_t)r * NN + c;
    unsigned mask = 1u << (bit & 31);
    unsigned old = atomicOr(&g_bitmap[bit >> 5], mask);
    if (!(old & mask)) {
        atomicAdd(&g_degc[r], 1);
        const float4* xp = (const float4*)&g_x6[c * 8];
        float4 a = xp[0], b = xp[1];
        atomicAdd(&g_agg[r * 8 + 0], a.x);
        atomicAdd(&g_agg[r * 8 + 1], a.y);
        atomicAdd(&g_agg[r * 8 + 2], a.z);
        atomicAdd(&g_agg[r * 8 + 3], a.w);
        atomicAdd(&g_agg[r * 8 + 4], b.x);
        atomicAdd(&g_agg[r * 8 + 5], b.y);
        atomicAdd(&g_agg[r * 8 + 6], b.z);
        atomicAdd(&g_agg[r * 8 + 7], b.w);
    }
}

// ---------------- kernel 10: final score + touched-state cleanup ----------------
__global__ void k_final_cleanup(const float* __restrict__ x1,
                                const float* __restrict__ lin2w,
                                float* __restrict__ out, int E) {
    int i = blockIdx.x * blockDim.x + threadIdx.x;
    if (i < NN) {
        float inv = 1.0f / (float)g_degc[i];
        float r2 = 0.f, gl = 0.f;
#pragma unroll
        for (int c = 0; c < 8; c++) {
            float a = g_agg[i * 8 + c];
            r2 += g_x6[i * 8 + c] * a;
            gl += (inv * a) * lin2w[c];
        }
        out[i] = r2 * inv + x1[i * 10] + gl;
    }
    if (i < E) {        // reset exactly the bitmap words touched this launch
        size_t bit = (size_t)g_rows[i] * NN + g_cols[i];
        g_bitmap[bit >> 5] = 0u;
    } else if (i < E + NN) {
        int n = i - E;
        size_t bit = (size_t)n * NN + (size_t)n;
        g_bitmap[bit >> 5] = 0u;
        g_deg[n] = 0;
    }
}

// ---------------- launch ----------------
extern "C" void kernel_launch(void* const* d_in, const int* in_sizes, int n_in,
                              void* d_out, int out_size) {
    const float* x1    = (const float*)d_in[0];
    const int*   eidx  = (const int*)d_in[2];
    const float* W1    = (const float*)d_in[4];
    const float* as1   = (const float*)d_in[5];
    const float* ad1   = (const float*)d_in[6];
    const float* b1    = (const float*)d_in[7];
    const float* W2    = (const float*)d_in[8];
    const float* as2   = (const float*)d_in[9];
    const float* ad2   = (const float*)d_in[10];
    const float* b2    = (const float*)d_in[11];
    const float* W3    = (const float*)d_in[12];
    const float* as3   = (const float*)d_in[13];
    const float* ad3   = (const float*)d_in[14];
    const float* b3    = (const float*)d_in[15];
    const float* lin2w = (const float*)d_in[16];
    float* out = (float*)d_out;

    int E = in_sizes[2] / 2;
    if (E > EMAX) E = EMAX;

    const int TB = 256;
    int big = (E > NN * 32) ? E : NN * 32;
    int g1  = (big + TB - 1) / TB;
    int gE  = (E + TB - 1) / TB;
    int gEN = (E + NN + TB - 1) / TB;
    int gA  = (NN * 32 + TB - 1) / TB;        // warp-per-node
    int g16 = (NN * 16 + TB - 1) / TB;
    int g8  = (NN * 8 + TB - 1) / TB;

    k_edges_t1<<<g1, TB>>>(eidx, E, x1, W1, as1, ad1);
    k_scan<<<1, 1024>>>();
    k_scatter<<<gEN, TB>>>(E);
    k_a1<<<gA, TB>>>(b1);
    k_t2<<<g16, TB>>>(W2, as2, ad2);
    k_a2<<<gA, TB>>>(b2);
    k_t3<<<g8, TB>>>(W3, as3, ad3);
    k_a3f<<<gA, TB>>>(b3);
    k_dedup<<<gE, TB>>>(E);
    k_final_cleanup<<<gEN, TB>>>(x1, lin2w, out, E);
}